// round 2
// baseline (speedup 1.0000x reference)
#include <cuda_runtime.h>
#include <math.h>

#define BB 256
#define NN 256
#define DIN 128
#define DHH 128
#define HH 4
#define HD 512

// ---------------- scratch (device globals; no allocation allowed) ----------------
__device__ float g_h[(size_t)BB * HH * NN * DHH];   // [b][h][j][d]  134 MB
__device__ float g_as[BB * HH * NN];                // [b][h][n]
__device__ float g_ad[BB * HH * NN];
__device__ float g_y[(size_t)BB * NN * HD];         // [b][n][hd]    134 MB
__device__ float g_hp[BB * NN];

// ================= Kernel 1: h = x @ W1 (per-head), + a_s/a_d epilogue =========
// grid (512, 4): blockIdx.x -> (b, n0), blockIdx.y -> head. 128 rows x 128 cols.
#define K1_SMEM ((128 * 129 + 128 * 128) * 4)
__global__ __launch_bounds__(256, 1) void k1_gemm(
    const float* __restrict__ x, const float* __restrict__ W1,
    const float* __restrict__ att_src, const float* __restrict__ att_dst) {
  extern __shared__ float sm[];
  float* xs = sm;             // [k][row] transposed, row-pitch 129 (conflict-free stores)
  float* ws = sm + 128 * 129; // [k][c]
  const int h = blockIdx.y;
  const int bx = blockIdx.x;
  const int b = bx >> 1;
  const int n0 = (bx & 1) << 7;
  const int tid = threadIdx.x;

  const float* xg = x + (size_t)(b * NN + n0) * DIN;
#pragma unroll
  for (int it = 0; it < 16; ++it) {
    int idx = it * 256 + tid;
    int row = idx >> 5;
    int k4 = (idx & 31) << 2;
    float4 v = *(const float4*)(xg + row * DIN + k4);
    xs[(k4 + 0) * 129 + row] = v.x;
    xs[(k4 + 1) * 129 + row] = v.y;
    xs[(k4 + 2) * 129 + row] = v.z;
    xs[(k4 + 3) * 129 + row] = v.w;
  }
#pragma unroll
  for (int it = 0; it < 16; ++it) {
    int idx = it * 256 + tid;
    int k = idx >> 5;
    int c4 = (idx & 31) << 2;
    *(float4*)(ws + k * 128 + c4) = *(const float4*)(W1 + (size_t)(k * HH + h) * DHH + c4);
  }
  __syncthreads();

  const int ty = tid >> 4, tx = tid & 15;
  const int r0 = ty << 3, c0 = tx << 3;
  float acc[8][8];
#pragma unroll
  for (int i = 0; i < 8; ++i)
#pragma unroll
    for (int j = 0; j < 8; ++j) acc[i][j] = 0.f;

#pragma unroll 4
  for (int k = 0; k < 128; ++k) {
    float a[8], bb[8];
#pragma unroll
    for (int i = 0; i < 8; ++i) a[i] = xs[k * 129 + r0 + i];
    float4 w0 = *(const float4*)(ws + k * 128 + c0);
    float4 w1 = *(const float4*)(ws + k * 128 + c0 + 4);
    bb[0] = w0.x; bb[1] = w0.y; bb[2] = w0.z; bb[3] = w0.w;
    bb[4] = w1.x; bb[5] = w1.y; bb[6] = w1.z; bb[7] = w1.w;
#pragma unroll
    for (int i = 0; i < 8; ++i)
#pragma unroll
      for (int j = 0; j < 8; ++j) acc[i][j] = fmaf(a[i], bb[j], acc[i][j]);
  }

  // write h tile ([b][h][row][d] layout)
#pragma unroll
  for (int i = 0; i < 8; ++i) {
    float* dst = g_h + (size_t)((b * HH + h) * NN + n0 + r0 + i) * DHH + c0;
    *(float4*)(dst + 0) = make_float4(acc[i][0], acc[i][1], acc[i][2], acc[i][3]);
    *(float4*)(dst + 4) = make_float4(acc[i][4], acc[i][5], acc[i][6], acc[i][7]);
  }

  // a_s / a_d epilogue: partial dot over this thread's 8 cols, reduce across tx (16 lanes)
  float asw[8], adw[8];
#pragma unroll
  for (int j = 0; j < 8; ++j) {
    asw[j] = att_src[h * DHH + c0 + j];
    adw[j] = att_dst[h * DHH + c0 + j];
  }
#pragma unroll
  for (int i = 0; i < 8; ++i) {
    float ss = 0.f, dd = 0.f;
#pragma unroll
    for (int j = 0; j < 8; ++j) {
      ss = fmaf(acc[i][j], asw[j], ss);
      dd = fmaf(acc[i][j], adw[j], dd);
    }
#pragma unroll
    for (int off = 8; off > 0; off >>= 1) {
      ss += __shfl_xor_sync(0xffffffffu, ss, off);
      dd += __shfl_xor_sync(0xffffffffu, dd, off);
    }
    if (tx == 0) {
      g_as[(b * HH + h) * NN + n0 + r0 + i] = ss;
      g_ad[(b * HH + h) * NN + n0 + r0 + i] = dd;
    }
  }
}

// ================= Kernel 2: softmax attention per (b,h) ======================
// out[i][d] = sum_j A[i][j] * h[j][d];  A via separable-exp trick (4 exps/node).
#define K2_SMEM ((NN * DHH + 64 * 128 + 6 * NN) * 4)
__global__ __launch_bounds__(256, 1) void k2_attn(const float* __restrict__ b1) {
  extern __shared__ float sm[];
  float* hs = sm;               // [256][128]
  float* A = sm + NN * DHH;     // [64][128]  A[j][i] within chunk
  float* asv = A + 64 * 128;
  float* adv = asv + NN;
  float* E1 = adv + NN;
  float* E2 = E1 + NN;
  float* F1 = E2 + NN;
  float* F2 = F1 + NN;
  const int bh = blockIdx.x;    // b*H + h
  const int h = bh & 3;
  const int b = bh >> 2;
  const int tid = threadIdx.x;

  const float* hg = g_h + (size_t)bh * NN * DHH;
#pragma unroll
  for (int it = 0; it < 32; ++it) {
    int idx = (it * 256 + tid) << 2;
    *(float4*)(hs + idx) = *(const float4*)(hg + idx);
  }
  asv[tid] = g_as[bh * NN + tid];
  adv[tid] = g_ad[bh * NN + tid];
  __syncthreads();

  const float as_i = asv[tid];
  E1[tid] = __expf(as_i);
  E2[tid] = __expf(0.2f * as_i);
  __syncthreads();

  // stability max: m_i = lrelu(ad_i + max_j as_j)   (lrelu monotone)
  float amax = -1e30f;
#pragma unroll 8
  for (int j = 0; j < NN; ++j) amax = fmaxf(amax, asv[j]);
  const float ad_i = adv[tid];
  const float T = ad_i + amax;
  const float m = T > 0.f ? T : 0.2f * T;
  const float f1 = __expf(ad_i - m);
  const float f2 = __expf(0.2f * ad_i - m);
  float SP = 0.f, SN = 0.f;
#pragma unroll 4
  for (int j = 0; j < NN; ++j) {
    float t = ad_i + asv[j];
    if (t > 0.f) SP += E1[j]; else SN += E2[j];
  }
  const float r = 1.0f / (f1 * SP + f2 * SN);
  F1[tid] = f1 * r;
  F2[tid] = f2 * r;
  __syncthreads();

  const int ty = tid >> 4, tx = tid & 15;
  const int r0 = ty << 3, c0 = tx << 3;
  float bias[8];
#pragma unroll
  for (int j = 0; j < 8; ++j) bias[j] = b1[h * DHH + c0 + j];

  for (int i0 = 0; i0 < NN; i0 += 128) {
    float acc[8][8];
#pragma unroll
    for (int i = 0; i < 8; ++i)
#pragma unroll
      for (int j = 0; j < 8; ++j) acc[i][j] = 0.f;

    for (int jt = 0; jt < 4; ++jt) {
      const int j0 = jt << 6;
      __syncthreads();
#pragma unroll
      for (int t2 = 0; t2 < 32; ++t2) {
        int idx = t2 * 256 + tid;
        int j = idx >> 7, i = idx & 127;
        float tt = adv[i0 + i] + asv[j0 + j];
        A[idx] = (tt > 0.f) ? F1[i0 + i] * E1[j0 + j] : F2[i0 + i] * E2[j0 + j];
      }
      __syncthreads();
#pragma unroll 2
      for (int j = 0; j < 64; ++j) {
        float4 a0 = *(const float4*)(A + j * 128 + r0);
        float4 a1 = *(const float4*)(A + j * 128 + r0 + 4);
        float4 h0 = *(const float4*)(hs + (j0 + j) * 128 + c0);
        float4 h1 = *(const float4*)(hs + (j0 + j) * 128 + c0 + 4);
        float af[8] = {a0.x, a0.y, a0.z, a0.w, a1.x, a1.y, a1.z, a1.w};
        float hf[8] = {h0.x, h0.y, h0.z, h0.w, h1.x, h1.y, h1.z, h1.w};
#pragma unroll
        for (int i = 0; i < 8; ++i)
#pragma unroll
          for (int d = 0; d < 8; ++d) acc[i][d] = fmaf(af[i], hf[d], acc[i][d]);
      }
    }
    // write out1 (+b1) as [b][n][hd]
#pragma unroll
    for (int i = 0; i < 8; ++i) {
      float* dst = g_y + (size_t)(b * NN + i0 + r0 + i) * HD + h * DHH + c0;
      *(float4*)(dst + 0) = make_float4(acc[i][0] + bias[0], acc[i][1] + bias[1],
                                        acc[i][2] + bias[2], acc[i][3] + bias[3]);
      *(float4*)(dst + 4) = make_float4(acc[i][4] + bias[4], acc[i][5] + bias[5],
                                        acc[i][6] + bias[6], acc[i][7] + bias[7]);
    }
  }
}

// ================= Kernel 3: LayerNorm + ELU + projection -> hp ===============
__global__ __launch_bounds__(256) void k3_ln(
    const float* __restrict__ gamma, const float* __restrict__ beta,
    const float* __restrict__ W2) {
  const int w = threadIdx.x >> 5, lane = threadIdx.x & 31;
  const int row = blockIdx.x * 8 + w;
  const float* yr = g_y + (size_t)row * HD;
  float4 v[4];
  float s = 0.f, sq = 0.f;
#pragma unroll
  for (int k = 0; k < 4; ++k) {
    v[k] = *(const float4*)(yr + (((k << 5) + lane) << 2));
    s += v[k].x + v[k].y + v[k].z + v[k].w;
    sq += v[k].x * v[k].x + v[k].y * v[k].y + v[k].z * v[k].z + v[k].w * v[k].w;
  }
#pragma unroll
  for (int off = 16; off > 0; off >>= 1) {
    s += __shfl_xor_sync(0xffffffffu, s, off);
    sq += __shfl_xor_sync(0xffffffffu, sq, off);
  }
  const float mu = s * (1.0f / 512.0f);
  const float var = sq * (1.0f / 512.0f) - mu * mu;
  const float rinv = rsqrtf(var + 1e-5f);
  float hp = 0.f;
#pragma unroll
  for (int k = 0; k < 4; ++k) {
    int c = (((k << 5) + lane) << 2);
    float4 g4 = *(const float4*)(gamma + c);
    float4 b4 = *(const float4*)(beta + c);
    float4 w4 = *(const float4*)(W2 + c);
    float t, e;
    t = (v[k].x - mu) * rinv * g4.x + b4.x; e = t > 0.f ? t : expm1f(t); hp = fmaf(e, w4.x, hp);
    t = (v[k].y - mu) * rinv * g4.y + b4.y; e = t > 0.f ? t : expm1f(t); hp = fmaf(e, w4.y, hp);
    t = (v[k].z - mu) * rinv * g4.z + b4.z; e = t > 0.f ? t : expm1f(t); hp = fmaf(e, w4.z, hp);
    t = (v[k].w - mu) * rinv * g4.w + b4.w; e = t > 0.f ? t : expm1f(t); hp = fmaf(e, w4.w, hp);
  }
#pragma unroll
  for (int off = 16; off > 0; off >>= 1) hp += __shfl_xor_sync(0xffffffffu, hp, off);
  if (lane == 0) g_hp[row] = hp;
}

// ================= Kernel 4: layer-2 scalar attention per batch ===============
__global__ __launch_bounds__(256) void k4_attn2(
    const float* __restrict__ att_src2, const float* __restrict__ att_dst2,
    const float* __restrict__ b2, float* __restrict__ out) {
  __shared__ float hp[NN], asv[NN], E1[NN], E2[NN], P1[NN], P2[NN];
  const int b = blockIdx.x, tid = threadIdx.x;
  const float v = g_hp[b * NN + tid];
  hp[tid] = v;
  const float a_src = att_src2[0], a_dst = att_dst2[0];
  const float as = v * a_src;
  asv[tid] = as;
  const float e1 = __expf(as), e2 = __expf(0.2f * as);
  E1[tid] = e1; E2[tid] = e2; P1[tid] = e1 * v; P2[tid] = e2 * v;
  __syncthreads();
  float amax = -1e30f;
#pragma unroll 8
  for (int j = 0; j < NN; ++j) amax = fmaxf(amax, asv[j]);
  const float ad = v * a_dst;
  const float T = ad + amax;
  const float m = T > 0.f ? T : 0.2f * T;
  const float f1 = __expf(ad - m), f2 = __expf(0.2f * ad - m);
  float SP = 0.f, SN = 0.f, NP = 0.f, NNa = 0.f;
#pragma unroll 4
  for (int j = 0; j < NN; ++j) {
    float t = ad + asv[j];
    if (t > 0.f) { SP += E1[j]; NP += P1[j]; }
    else         { SN += E2[j]; NNa += P2[j]; }
  }
  out[b * NN + tid] = (f1 * NP + f2 * NNa) / (f1 * SP + f2 * SN) + b2[0];
}

// ================================ launch ======================================
extern "C" void kernel_launch(void* const* d_in, const int* in_sizes, int n_in,
                              void* d_out, int out_size) {
  const float* x    = (const float*)d_in[0];
  // d_in[1] = adj (ignored by the reference)
  const float* W1   = (const float*)d_in[2];
  const float* as1  = (const float*)d_in[3];
  const float* ad1  = (const float*)d_in[4];
  const float* b1   = (const float*)d_in[5];
  const float* gam  = (const float*)d_in[6];
  const float* bet  = (const float*)d_in[7];
  const float* W2   = (const float*)d_in[8];
  const float* as2  = (const float*)d_in[9];
  const float* ad2  = (const float*)d_in[10];
  const float* b2   = (const float*)d_in[11];
  float* out = (float*)d_out;

  cudaFuncSetAttribute(k1_gemm, cudaFuncAttributeMaxDynamicSharedMemorySize, K1_SMEM);
  cudaFuncSetAttribute(k2_attn, cudaFuncAttributeMaxDynamicSharedMemorySize, K2_SMEM);

  k1_gemm<<<dim3(512, 4, 1), 256, K1_SMEM>>>(x, W1, as1, ad1);
  k2_attn<<<BB * HH, 256, K2_SMEM>>>(b1);
  k3_ln<<<BB * NN / 8, 256>>>(gam, bet, W2);
  k4_attn2<<<BB, 256>>>(as2, ad2, b2, out);
}

// round 3
// speedup vs baseline: 1.2820x; 1.2820x over previous
#include <cuda_runtime.h>
#include <math.h>

#define BB 256
#define NN 256
#define DIN 128
#define DHH 128
#define HH 4
#define HD 512

// ---------------- scratch (device globals; no allocation allowed) ----------------
__device__ float g_h[(size_t)BB * HH * NN * DHH];   // [b][h][j][d]  134 MB
__device__ float g_as[BB * HH * NN];                // [b][h][n]
__device__ float g_ad[BB * HH * NN];
__device__ float g_y[(size_t)BB * NN * HD];         // [b][n][hd]    134 MB
__device__ float g_hp[BB * NN];

// ================= Kernel 1: h = x @ W1 (per-head), + a_s/a_d epilogue =========
#define K1_SMEM ((128 * 129 + 128 * 128) * 4)
__global__ __launch_bounds__(256, 1) void k1_gemm(
    const float* __restrict__ x, const float* __restrict__ W1,
    const float* __restrict__ att_src, const float* __restrict__ att_dst) {
  extern __shared__ float sm[];
  float* xs = sm;             // [k][row] transposed, pitch 129
  float* ws = sm + 128 * 129; // [k][c]
  const int h = blockIdx.y;
  const int bx = blockIdx.x;
  const int b = bx >> 1;
  const int n0 = (bx & 1) << 7;
  const int tid = threadIdx.x;

  const float* xg = x + (size_t)(b * NN + n0) * DIN;
#pragma unroll
  for (int it = 0; it < 16; ++it) {
    int idx = it * 256 + tid;
    int row = idx >> 5;
    int k4 = (idx & 31) << 2;
    float4 v = *(const float4*)(xg + row * DIN + k4);
    xs[(k4 + 0) * 129 + row] = v.x;
    xs[(k4 + 1) * 129 + row] = v.y;
    xs[(k4 + 2) * 129 + row] = v.z;
    xs[(k4 + 3) * 129 + row] = v.w;
  }
#pragma unroll
  for (int it = 0; it < 16; ++it) {
    int idx = it * 256 + tid;
    int k = idx >> 5;
    int c4 = (idx & 31) << 2;
    *(float4*)(ws + k * 128 + c4) = *(const float4*)(W1 + (size_t)(k * HH + h) * DHH + c4);
  }
  __syncthreads();

  const int ty = tid >> 4, tx = tid & 15;
  const int r0 = ty << 3, c0 = tx << 3;
  float acc[8][8];
#pragma unroll
  for (int i = 0; i < 8; ++i)
#pragma unroll
    for (int j = 0; j < 8; ++j) acc[i][j] = 0.f;

#pragma unroll 4
  for (int k = 0; k < 128; ++k) {
    float a[8], bb[8];
#pragma unroll
    for (int i = 0; i < 8; ++i) a[i] = xs[k * 129 + r0 + i];
    float4 w0 = *(const float4*)(ws + k * 128 + c0);
    float4 w1 = *(const float4*)(ws + k * 128 + c0 + 4);
    bb[0] = w0.x; bb[1] = w0.y; bb[2] = w0.z; bb[3] = w0.w;
    bb[4] = w1.x; bb[5] = w1.y; bb[6] = w1.z; bb[7] = w1.w;
#pragma unroll
    for (int i = 0; i < 8; ++i)
#pragma unroll
      for (int j = 0; j < 8; ++j) acc[i][j] = fmaf(a[i], bb[j], acc[i][j]);
  }

#pragma unroll
  for (int i = 0; i < 8; ++i) {
    float* dst = g_h + (size_t)((b * HH + h) * NN + n0 + r0 + i) * DHH + c0;
    *(float4*)(dst + 0) = make_float4(acc[i][0], acc[i][1], acc[i][2], acc[i][3]);
    *(float4*)(dst + 4) = make_float4(acc[i][4], acc[i][5], acc[i][6], acc[i][7]);
  }

  float asw[8], adw[8];
#pragma unroll
  for (int j = 0; j < 8; ++j) {
    asw[j] = att_src[h * DHH + c0 + j];
    adw[j] = att_dst[h * DHH + c0 + j];
  }
#pragma unroll
  for (int i = 0; i < 8; ++i) {
    float ss = 0.f, dd = 0.f;
#pragma unroll
    for (int j = 0; j < 8; ++j) {
      ss = fmaf(acc[i][j], asw[j], ss);
      dd = fmaf(acc[i][j], adw[j], dd);
    }
#pragma unroll
    for (int off = 8; off > 0; off >>= 1) {
      ss += __shfl_xor_sync(0xffffffffu, ss, off);
      dd += __shfl_xor_sync(0xffffffffu, dd, off);
    }
    if (tx == 0) {
      g_as[(b * HH + h) * NN + n0 + r0 + i] = ss;
      g_ad[(b * HH + h) * NN + n0 + r0 + i] = dd;
    }
  }
}

// ================= Kernel 2: sorted-prefix softmax aggregation ================
// out[i,:] = F1[i]*(T1 - P1[c_i]) + F2[i]*P2[c_i], prefix sums in as-sorted order.
// O(N*D) instead of O(N^2*D).
#define K2_FLOATS (NN * DHH + NN * 9 + 2 * (NN + 1) + NN)
#define K2_SMEM (K2_FLOATS * 4)
__global__ __launch_bounds__(256, 1) void k2_sweep(const float* __restrict__ b1) {
  extern __shared__ float sm[];
  float* hs   = sm;                       // [256][128]
  float* asv  = sm + NN * DHH;            // 256
  float* adv  = asv + NN;                 // 256
  float* skey = adv + NN;                 // 256 sorted as keys
  int*   jidx = (int*)(skey + NN);        // 256 sorted j indices
  float* E1s  = (float*)(jidx + NN);      // 256 exp(as) sorted
  float* E2s  = E1s + NN;                 // 256 exp(0.2as) sorted
  float* cS1  = E2s + NN;                 // 257 exclusive prefix of E1s
  float* cS2  = cS1 + (NN + 1);           // 257
  float* stmp = cS2 + (NN + 1);           // 256 scan scratch (8 used)
  float* F1v  = stmp + NN;                // 256
  float* F2v  = F1v + NN;                 // 256
  int*   ckey = (int*)(F2v + NN);         // 256 packed (c<<16)|i

  const int bh = blockIdx.x;
  const int h = bh & 3;
  const int b = bh >> 2;
  const int tid = threadIdx.x;
  const int lane = tid & 31, warp = tid >> 5;

  // ---- load h, as, ad ----
  const float* hg = g_h + (size_t)bh * NN * DHH;
#pragma unroll
  for (int it = 0; it < 32; ++it) {
    int idx = (it * 256 + tid) << 2;
    *(float4*)(hs + idx) = *(const float4*)(hg + idx);
  }
  asv[tid] = g_as[bh * NN + tid];
  adv[tid] = g_ad[bh * NN + tid];
  skey[tid] = g_as[bh * NN + tid];
  jidx[tid] = tid;
  __syncthreads();

  // ---- bitonic sort (skey asc, carry jidx) ----
#pragma unroll
  for (int size = 2; size <= NN; size <<= 1) {
#pragma unroll
    for (int stride = size >> 1; stride > 0; stride >>= 1) {
      int partner = tid ^ stride;
      if (partner > tid) {
        bool asc = ((tid & size) == 0);
        float k0 = skey[tid], k1 = skey[partner];
        if ((k0 > k1) == asc) {
          skey[tid] = k1; skey[partner] = k0;
          int j0 = jidx[tid], j1 = jidx[partner];
          jidx[tid] = j1; jidx[partner] = j0;
        }
      }
      __syncthreads();
    }
  }

  // ---- exps in sorted order ----
  {
    float k = skey[tid];
    E1s[tid] = __expf(k);
    E2s[tid] = __expf(0.2f * k);
  }
  __syncthreads();

  // ---- scalar scans (warp-shuffle Hillis-Steele) ----
  {
    float v1 = E1s[tid], v2 = E2s[tid];
#pragma unroll
    for (int off = 1; off < 32; off <<= 1) {
      float n1 = __shfl_up_sync(0xffffffffu, v1, off);
      float n2 = __shfl_up_sync(0xffffffffu, v2, off);
      if (lane >= off) { v1 += n1; v2 += n2; }
    }
    if (lane == 31) { stmp[warp] = v1; stmp[8 + warp] = v2; }
    __syncthreads();
    if (warp == 0 && lane < 8) {
      float w1 = stmp[lane], w2 = stmp[8 + lane];
#pragma unroll
      for (int off = 1; off < 8; off <<= 1) {
        float n1 = __shfl_up_sync(0xffu, w1, off);
        float n2 = __shfl_up_sync(0xffu, w2, off);
        if (lane >= off) { w1 += n1; w2 += n2; }
      }
      stmp[lane] = w1; stmp[8 + lane] = w2;
    }
    __syncthreads();
    float base1 = (warp > 0) ? stmp[warp - 1] : 0.f;
    float base2 = (warp > 0) ? stmp[8 + warp - 1] : 0.f;
    cS1[tid + 1] = v1 + base1;   // inclusive -> exclusive shift
    cS2[tid + 1] = v2 + base2;
    if (tid == 0) { cS1[0] = 0.f; cS2[0] = 0.f; }
  }
  __syncthreads();

  // ---- per-row scalars: c_i via binary search, normalized F1/F2 ----
  {
    const float ad = adv[tid];
    const float xneg = -ad;
    int lo = 0, hi = NN;
#pragma unroll
    for (int s = 0; s < 8; ++s) {
      int mid = (lo + hi) >> 1;
      if (skey[mid] > xneg) hi = mid; else lo = mid + 1;
    }
    int c = lo;
    float SP = cS1[NN] - cS1[c];
    float SN = cS2[c];
    float f1 = __expf(ad);
    float f2 = __expf(0.2f * ad);
    float r = 1.0f / (f1 * SP + f2 * SN);
    F1v[tid] = f1 * r;
    F2v[tid] = f2 * r;
    ckey[tid] = (c << 16) | tid;
  }
  __syncthreads();

  // ---- bitonic sort ckey (int asc; rows grouped by c) ----
#pragma unroll
  for (int size = 2; size <= NN; size <<= 1) {
#pragma unroll
    for (int stride = size >> 1; stride > 0; stride >>= 1) {
      int partner = tid ^ stride;
      if (partner > tid) {
        bool asc = ((tid & size) == 0);
        int k0 = ckey[tid], k1 = ckey[partner];
        if ((k0 > k1) == asc) { ckey[tid] = k1; ckey[partner] = k0; }
      }
      __syncthreads();
    }
  }

  // ---- sweeps: threads 0..127 own one d each ----
  if (tid < DHH) {
    const int d = tid;
    const float bias_d = b1[h * DHH + d];
    float* yb = g_y + (size_t)b * NN * HD + h * DHH + d;

    // pass A: total T1 in sorted order (matches sweep prefix bitwise)
    float T1 = 0.f;
#pragma unroll 4
    for (int p = 0; p < NN; ++p) {
      int jp = jidx[p];
      T1 = fmaf(E1s[p], hs[jp * DHH + d], T1);
    }

    // pass B: prefix sweep with bucketed emissions
    float S1 = 0.f, S2 = 0.f;
    int q = 0;
    for (int p = 0; p < NN; ++p) {
      while (q < NN) {
        int ck = ckey[q];
        if ((ck >> 16) != p) break;
        int i = ck & 0xffff;
        float val = fmaf(F1v[i], T1 - S1, F2v[i] * S2) + bias_d;
        yb[(size_t)i * HD] = val;
        ++q;
      }
      int jp = jidx[p];
      float hv = hs[jp * DHH + d];
      S1 = fmaf(E1s[p], hv, S1);
      S2 = fmaf(E2s[p], hv, S2);
    }
    while (q < NN) {  // c == 256 rows: T1-S1 is exactly 0
      int ck = ckey[q];
      int i = ck & 0xffff;
      float val = fmaf(F1v[i], T1 - S1, F2v[i] * S2) + bias_d;
      yb[(size_t)i * HD] = val;
      ++q;
    }
  }
}

// ================= Kernel 3: LayerNorm + ELU + projection -> hp ===============
__global__ __launch_bounds__(256) void k3_ln(
    const float* __restrict__ gamma, const float* __restrict__ beta,
    const float* __restrict__ W2) {
  const int w = threadIdx.x >> 5, lane = threadIdx.x & 31;
  const int row = blockIdx.x * 8 + w;
  const float* yr = g_y + (size_t)row * HD;
  float4 v[4];
  float s = 0.f, sq = 0.f;
#pragma unroll
  for (int k = 0; k < 4; ++k) {
    v[k] = *(const float4*)(yr + (((k << 5) + lane) << 2));
    s += v[k].x + v[k].y + v[k].z + v[k].w;
    sq += v[k].x * v[k].x + v[k].y * v[k].y + v[k].z * v[k].z + v[k].w * v[k].w;
  }
#pragma unroll
  for (int off = 16; off > 0; off >>= 1) {
    s += __shfl_xor_sync(0xffffffffu, s, off);
    sq += __shfl_xor_sync(0xffffffffu, sq, off);
  }
  const float mu = s * (1.0f / 512.0f);
  const float var = sq * (1.0f / 512.0f) - mu * mu;
  const float rinv = rsqrtf(var + 1e-5f);
  float hp = 0.f;
#pragma unroll
  for (int k = 0; k < 4; ++k) {
    int c = (((k << 5) + lane) << 2);
    float4 g4 = *(const float4*)(gamma + c);
    float4 b4 = *(const float4*)(beta + c);
    float4 w4 = *(const float4*)(W2 + c);
    float t, e;
    t = (v[k].x - mu) * rinv * g4.x + b4.x; e = t > 0.f ? t : expm1f(t); hp = fmaf(e, w4.x, hp);
    t = (v[k].y - mu) * rinv * g4.y + b4.y; e = t > 0.f ? t : expm1f(t); hp = fmaf(e, w4.y, hp);
    t = (v[k].z - mu) * rinv * g4.z + b4.z; e = t > 0.f ? t : expm1f(t); hp = fmaf(e, w4.z, hp);
    t = (v[k].w - mu) * rinv * g4.w + b4.w; e = t > 0.f ? t : expm1f(t); hp = fmaf(e, w4.w, hp);
  }
#pragma unroll
  for (int off = 16; off > 0; off >>= 1) hp += __shfl_xor_sync(0xffffffffu, hp, off);
  if (lane == 0) g_hp[row] = hp;
}

// ================= Kernel 4: layer-2 scalar attention per batch ===============
__global__ __launch_bounds__(256) void k4_attn2(
    const float* __restrict__ att_src2, const float* __restrict__ att_dst2,
    const float* __restrict__ b2, float* __restrict__ out) {
  __shared__ float hp[NN], asv[NN], E1[NN], E2[NN], P1[NN], P2[NN];
  const int b = blockIdx.x, tid = threadIdx.x;
  const float v = g_hp[b * NN + tid];
  hp[tid] = v;
  const float a_src = att_src2[0], a_dst = att_dst2[0];
  const float as = v * a_src;
  asv[tid] = as;
  const float e1 = __expf(as), e2 = __expf(0.2f * as);
  E1[tid] = e1; E2[tid] = e2; P1[tid] = e1 * v; P2[tid] = e2 * v;
  __syncthreads();
  const float ad = v * a_dst;
  float SP = 0.f, SN = 0.f, NP = 0.f, NNa = 0.f;
#pragma unroll 4
  for (int j = 0; j < NN; ++j) {
    float t = ad + asv[j];
    if (t > 0.f) { SP += E1[j]; NP += P1[j]; }
    else         { SN += E2[j]; NNa += P2[j]; }
  }
  const float f1 = __expf(ad), f2 = __expf(0.2f * ad);
  out[b * NN + tid] = (f1 * NP + f2 * NNa) / (f1 * SP + f2 * SN) + b2[0];
}

// ================================ launch ======================================
extern "C" void kernel_launch(void* const* d_in, const int* in_sizes, int n_in,
                              void* d_out, int out_size) {
  const float* x    = (const float*)d_in[0];
  const float* W1   = (const float*)d_in[2];
  const float* as1  = (const float*)d_in[3];
  const float* ad1  = (const float*)d_in[4];
  const float* b1   = (const float*)d_in[5];
  const float* gam  = (const float*)d_in[6];
  const float* bet  = (const float*)d_in[7];
  const float* W2   = (const float*)d_in[8];
  const float* as2  = (const float*)d_in[9];
  const float* ad2  = (const float*)d_in[10];
  const float* b2   = (const float*)d_in[11];
  float* out = (float*)d_out;

  cudaFuncSetAttribute(k1_gemm, cudaFuncAttributeMaxDynamicSharedMemorySize, K1_SMEM);
  cudaFuncSetAttribute(k2_sweep, cudaFuncAttributeMaxDynamicSharedMemorySize, K2_SMEM);

  k1_gemm<<<dim3(512, 4, 1), 256, K1_SMEM>>>(x, W1, as1, ad1);
  k2_sweep<<<BB * HH, 256, K2_SMEM>>>(b1);
  k3_ln<<<BB * NN / 8, 256>>>(gam, bet, W2);
  k4_attn2<<<BB, 256>>>(as2, ad2, b2, out);
}

// round 4
// speedup vs baseline: 1.5171x; 1.1833x over previous
#include <cuda_runtime.h>
#include <math.h>

#define BB 256
#define NN 256
#define DIN 128
#define DHH 128
#define HH 4
#define HD 512

// ---------------- scratch (device globals; no allocation allowed) ----------------
__device__ float g_h[(size_t)BB * HH * NN * DHH];   // [b][h][j][d]  134 MB
__device__ float g_as[BB * HH * NN];                // [b][h][n]
__device__ float g_ad[BB * HH * NN];
__device__ float g_y[(size_t)BB * NN * HD];         // [b][n][hd]    134 MB
__device__ float g_hp[BB * NN];

// ================= Kernel 1: h = x @ W1 (per-head), + a_s/a_d epilogue =========
#define K1_SMEM ((128 * 129 + 128 * 128) * 4)
__global__ __launch_bounds__(256, 1) void k1_gemm(
    const float* __restrict__ x, const float* __restrict__ W1,
    const float* __restrict__ att_src, const float* __restrict__ att_dst) {
  extern __shared__ float sm[];
  float* xs = sm;             // [k][row] transposed, pitch 129
  float* ws = sm + 128 * 129; // [k][c]
  const int h = blockIdx.y;
  const int bx = blockIdx.x;
  const int b = bx >> 1;
  const int n0 = (bx & 1) << 7;
  const int tid = threadIdx.x;

  const float* xg = x + (size_t)(b * NN + n0) * DIN;
#pragma unroll
  for (int it = 0; it < 16; ++it) {
    int idx = it * 256 + tid;
    int row = idx >> 5;
    int k4 = (idx & 31) << 2;
    float4 v = *(const float4*)(xg + row * DIN + k4);
    xs[(k4 + 0) * 129 + row] = v.x;
    xs[(k4 + 1) * 129 + row] = v.y;
    xs[(k4 + 2) * 129 + row] = v.z;
    xs[(k4 + 3) * 129 + row] = v.w;
  }
#pragma unroll
  for (int it = 0; it < 16; ++it) {
    int idx = it * 256 + tid;
    int k = idx >> 5;
    int c4 = (idx & 31) << 2;
    *(float4*)(ws + k * 128 + c4) = *(const float4*)(W1 + (size_t)(k * HH + h) * DHH + c4);
  }
  __syncthreads();

  const int ty = tid >> 4, tx = tid & 15;
  const int r0 = ty << 3, c0 = tx << 3;
  float acc[8][8];
#pragma unroll
  for (int i = 0; i < 8; ++i)
#pragma unroll
    for (int j = 0; j < 8; ++j) acc[i][j] = 0.f;

#pragma unroll 4
  for (int k = 0; k < 128; ++k) {
    float a[8], bb[8];
#pragma unroll
    for (int i = 0; i < 8; ++i) a[i] = xs[k * 129 + r0 + i];
    float4 w0 = *(const float4*)(ws + k * 128 + c0);
    float4 w1 = *(const float4*)(ws + k * 128 + c0 + 4);
    bb[0] = w0.x; bb[1] = w0.y; bb[2] = w0.z; bb[3] = w0.w;
    bb[4] = w1.x; bb[5] = w1.y; bb[6] = w1.z; bb[7] = w1.w;
#pragma unroll
    for (int i = 0; i < 8; ++i)
#pragma unroll
      for (int j = 0; j < 8; ++j) acc[i][j] = fmaf(a[i], bb[j], acc[i][j]);
  }

#pragma unroll
  for (int i = 0; i < 8; ++i) {
    float* dst = g_h + (size_t)((b * HH + h) * NN + n0 + r0 + i) * DHH + c0;
    *(float4*)(dst + 0) = make_float4(acc[i][0], acc[i][1], acc[i][2], acc[i][3]);
    *(float4*)(dst + 4) = make_float4(acc[i][4], acc[i][5], acc[i][6], acc[i][7]);
  }

  float asw[8], adw[8];
#pragma unroll
  for (int j = 0; j < 8; ++j) {
    asw[j] = att_src[h * DHH + c0 + j];
    adw[j] = att_dst[h * DHH + c0 + j];
  }
#pragma unroll
  for (int i = 0; i < 8; ++i) {
    float ss = 0.f, dd = 0.f;
#pragma unroll
    for (int j = 0; j < 8; ++j) {
      ss = fmaf(acc[i][j], asw[j], ss);
      dd = fmaf(acc[i][j], adw[j], dd);
    }
#pragma unroll
    for (int off = 8; off > 0; off >>= 1) {
      ss += __shfl_xor_sync(0xffffffffu, ss, off);
      dd += __shfl_xor_sync(0xffffffffu, dd, off);
    }
    if (tx == 0) {
      g_as[(b * HH + h) * NN + n0 + r0 + i] = ss;
      g_ad[(b * HH + h) * NN + n0 + r0 + i] = dd;
    }
  }
}

// ================= Kernel 2 v2: chunked sorted-prefix softmax aggregation ======
// out[i,:] = F1[i]*(T1 - P1[c_i]) + F2[i]*P2[c_i]; prefixes via 16-chunk
// checkpoints + per-phase smem-staged remainders. O(N*D), fully parallel.
__global__ __launch_bounds__(256, 4) void k2_sweep(const float* __restrict__ b1) {
  __shared__ float skey[NN];          // sorted as keys
  __shared__ int   jidx[NN];          // sorted j indices
  __shared__ float E1s[NN], E2s[NN];  // exps in sorted order
  __shared__ float cS1[NN + 1], cS2[NN + 1];  // scalar exclusive prefixes
  __shared__ float stmp[16];
  __shared__ float F1v[NN], F2v[NN];  // per original row i
  __shared__ int   ckey[NN];          // (c<<16)|i sorted asc
  __shared__ int   startv[18];        // phase boundaries
  __shared__ float CP1[17 * 128], CP2[17 * 128];  // vector chunk prefixes
  __shared__ float hbuf[16 * 128];    // staged h rows for current phase

  const int bh = blockIdx.x;
  const int h = bh & 3;
  const int b = bh >> 2;
  const int tid = threadIdx.x;
  const int lane = tid & 31, warp = tid >> 5;
  const float* hb = g_h + (size_t)bh * NN * DHH;

  skey[tid] = g_as[bh * NN + tid];
  jidx[tid] = tid;
  __syncthreads();

  // ---- bitonic sort #1: skey asc, carry jidx ----
#pragma unroll
  for (int size = 2; size <= NN; size <<= 1) {
#pragma unroll
    for (int stride = size >> 1; stride > 0; stride >>= 1) {
      int partner = tid ^ stride;
      if (partner > tid) {
        bool asc = ((tid & size) == 0);
        float k0 = skey[tid], k1 = skey[partner];
        if ((k0 > k1) == asc) {
          skey[tid] = k1; skey[partner] = k0;
          int j0 = jidx[tid], j1 = jidx[partner];
          jidx[tid] = j1; jidx[partner] = j0;
        }
      }
      __syncthreads();
    }
  }

  {
    float k = skey[tid];
    E1s[tid] = __expf(k);
    E2s[tid] = __expf(0.2f * k);
  }
  __syncthreads();

  // ---- scalar scans (warp-shuffle) ----
  {
    float v1 = E1s[tid], v2 = E2s[tid];
#pragma unroll
    for (int off = 1; off < 32; off <<= 1) {
      float n1 = __shfl_up_sync(0xffffffffu, v1, off);
      float n2 = __shfl_up_sync(0xffffffffu, v2, off);
      if (lane >= off) { v1 += n1; v2 += n2; }
    }
    if (lane == 31) { stmp[warp] = v1; stmp[8 + warp] = v2; }
    __syncthreads();
    if (warp == 0 && lane < 8) {
      float w1 = stmp[lane], w2 = stmp[8 + lane];
#pragma unroll
      for (int off = 1; off < 8; off <<= 1) {
        float n1 = __shfl_up_sync(0xffu, w1, off);
        float n2 = __shfl_up_sync(0xffu, w2, off);
        if (lane >= off) { w1 += n1; w2 += n2; }
      }
      stmp[lane] = w1; stmp[8 + lane] = w2;
    }
    __syncthreads();
    float base1 = (warp > 0) ? stmp[warp - 1] : 0.f;
    float base2 = (warp > 0) ? stmp[8 + warp - 1] : 0.f;
    cS1[tid + 1] = v1 + base1;
    cS2[tid + 1] = v2 + base2;
    if (tid == 0) { cS1[0] = 0.f; cS2[0] = 0.f; }
  }
  __syncthreads();

  // ---- per-row scalars: binary search for c_i, normalized F1/F2 ----
  {
    const float ad = g_ad[bh * NN + tid];
    const float xneg = -ad;
    int lo = 0, hi = NN;
#pragma unroll
    for (int s = 0; s < 8; ++s) {
      int mid = (lo + hi) >> 1;
      if (skey[mid] > xneg) hi = mid; else lo = mid + 1;
    }
    int c = lo;
    float SP = cS1[NN] - cS1[c];
    float SN = cS2[c];
    float f1 = __expf(ad);
    float f2 = __expf(0.2f * ad);
    float r = 1.0f / (f1 * SP + f2 * SN);
    F1v[tid] = f1 * r;
    F2v[tid] = f2 * r;
    ckey[tid] = (c << 16) | tid;
  }
  __syncthreads();

  // ---- vector chunk checkpoints: CP[k] = prefix over chunks 0..k-1 ----
  {
    const int d = tid & 127, half = tid >> 7;
#pragma unroll
    for (int cc = 0; cc < 8; ++cc) {
      const int c = half * 8 + cc;
      float s1 = 0.f, s2 = 0.f;
#pragma unroll
      for (int t = 0; t < 16; ++t) {
        int p = (c << 4) + t;
        int jp = jidx[p];
        float hv = __ldg(hb + (size_t)jp * DHH + d);
        s1 = fmaf(E1s[p], hv, s1);
        s2 = fmaf(E2s[p], hv, s2);
      }
      CP1[(c + 1) * 128 + d] = s1;
      CP2[(c + 1) * 128 + d] = s2;
    }
  }
  __syncthreads();
  if (tid < 128) {
    float run1 = 0.f, run2 = 0.f;
    CP1[tid] = 0.f; CP2[tid] = 0.f;
#pragma unroll
    for (int k = 1; k <= 16; ++k) {
      run1 += CP1[k * 128 + tid]; CP1[k * 128 + tid] = run1;
      run2 += CP2[k * 128 + tid]; CP2[k * 128 + tid] = run2;
    }
  }
  __syncthreads();

  // ---- bitonic sort #2: ckey asc (groups rows by cutoff chunk) ----
#pragma unroll
  for (int size = 2; size <= NN; size <<= 1) {
#pragma unroll
    for (int stride = size >> 1; stride > 0; stride >>= 1) {
      int partner = tid ^ stride;
      if (partner > tid) {
        bool asc = ((tid & size) == 0);
        int k0 = ckey[tid], k1 = ckey[partner];
        if ((k0 > k1) == asc) { ckey[tid] = k1; ckey[partner] = k0; }
      }
      __syncthreads();
    }
  }
  // phase boundaries: startv[t] = first sorted idx with c >= t*16
  if (tid < 17) {
    int target = (tid * 16) << 16;
    int lo = 0, hi = NN;
    while (lo < hi) { int mid = (lo + hi) >> 1; if (ckey[mid] < target) lo = mid + 1; else hi = mid; }
    startv[tid] = lo;
  }
  if (tid == 17) startv[17] = NN;
  __syncthreads();

  // ---- emission in 16 staged phases + exact tail phase ----
  const int tg = tid >> 7, d = tid & 127;
  const float bias_d = b1[(h << 7) + d];
  const float T1d = CP1[(16 << 7) + d];
  float* yb = g_y + (size_t)b * NN * HD + (h << 7) + d;

  for (int ch = 0; ch < 16; ++ch) {
    const int lo = startv[ch], hi = startv[ch + 1];
    __syncthreads();  // protect hbuf from previous-phase readers
    if (lo < hi) {
#pragma unroll
      for (int q = tid; q < 2048; q += 256) {
        int p = (ch << 4) + (q >> 7);
        int jp = jidx[p];
        hbuf[q] = __ldg(hb + (size_t)jp * DHH + (q & 127));
      }
    }
    __syncthreads();
    for (int r = lo + tg; r < hi; r += 2) {
      int ck = ckey[r];
      int i = ck & 0xffff;
      int c = ck >> 16;
      float P1 = CP1[(ch << 7) + d], P2 = CP2[(ch << 7) + d];
#pragma unroll 4
      for (int p = ch << 4; p < c; ++p) {
        float hv = hbuf[((p - (ch << 4)) << 7) + d];
        P1 = fmaf(E1s[p], hv, P1);
        P2 = fmaf(E2s[p], hv, P2);
      }
      yb[(size_t)i * HD] = fmaf(F1v[i], T1d - P1, F2v[i] * P2) + bias_d;
    }
  }
  // c == 256: T1 - P1 is exactly zero (same word)
  {
    const float P2t = CP2[(16 << 7) + d];
    for (int r = startv[16] + tg; r < NN; r += 2) {
      int i = ckey[r] & 0xffff;
      yb[(size_t)i * HD] = F2v[i] * P2t + bias_d;
    }
  }
}

// ================= Kernel 3: LayerNorm + ELU + projection -> hp ===============
__global__ __launch_bounds__(256) void k3_ln(
    const float* __restrict__ gamma, const float* __restrict__ beta,
    const float* __restrict__ W2) {
  const int w = threadIdx.x >> 5, lane = threadIdx.x & 31;
  const int row = blockIdx.x * 8 + w;
  const float* yr = g_y + (size_t)row * HD;
  float4 v[4];
  float s = 0.f, sq = 0.f;
#pragma unroll
  for (int k = 0; k < 4; ++k) {
    v[k] = *(const float4*)(yr + (((k << 5) + lane) << 2));
    s += v[k].x + v[k].y + v[k].z + v[k].w;
    sq += v[k].x * v[k].x + v[k].y * v[k].y + v[k].z * v[k].z + v[k].w * v[k].w;
  }
#pragma unroll
  for (int off = 16; off > 0; off >>= 1) {
    s += __shfl_xor_sync(0xffffffffu, s, off);
    sq += __shfl_xor_sync(0xffffffffu, sq, off);
  }
  const float mu = s * (1.0f / 512.0f);
  const float var = sq * (1.0f / 512.0f) - mu * mu;
  const float rinv = rsqrtf(var + 1e-5f);
  float hp = 0.f;
#pragma unroll
  for (int k = 0; k < 4; ++k) {
    int c = (((k << 5) + lane) << 2);
    float4 g4 = *(const float4*)(gamma + c);
    float4 b4 = *(const float4*)(beta + c);
    float4 w4 = *(const float4*)(W2 + c);
    float t, e;
    t = (v[k].x - mu) * rinv * g4.x + b4.x; e = t > 0.f ? t : expm1f(t); hp = fmaf(e, w4.x, hp);
    t = (v[k].y - mu) * rinv * g4.y + b4.y; e = t > 0.f ? t : expm1f(t); hp = fmaf(e, w4.y, hp);
    t = (v[k].z - mu) * rinv * g4.z + b4.z; e = t > 0.f ? t : expm1f(t); hp = fmaf(e, w4.z, hp);
    t = (v[k].w - mu) * rinv * g4.w + b4.w; e = t > 0.f ? t : expm1f(t); hp = fmaf(e, w4.w, hp);
  }
#pragma unroll
  for (int off = 16; off > 0; off >>= 1) hp += __shfl_xor_sync(0xffffffffu, hp, off);
  if (lane == 0) g_hp[row] = hp;
}

// ================= Kernel 4: layer-2 scalar attention per batch ===============
__global__ __launch_bounds__(256) void k4_attn2(
    const float* __restrict__ att_src2, const float* __restrict__ att_dst2,
    const float* __restrict__ b2, float* __restrict__ out) {
  __shared__ float asv[NN], E1[NN], E2[NN], P1[NN], P2[NN];
  const int b = blockIdx.x, tid = threadIdx.x;
  const float v = g_hp[b * NN + tid];
  const float a_src = att_src2[0], a_dst = att_dst2[0];
  const float as = v * a_src;
  asv[tid] = as;
  const float e1 = __expf(as), e2 = __expf(0.2f * as);
  E1[tid] = e1; E2[tid] = e2; P1[tid] = e1 * v; P2[tid] = e2 * v;
  __syncthreads();
  const float ad = v * a_dst;
  float SP = 0.f, SN = 0.f, NP = 0.f, NNa = 0.f;
#pragma unroll 4
  for (int j = 0; j < NN; ++j) {
    float t = ad + asv[j];
    if (t > 0.f) { SP += E1[j]; NP += P1[j]; }
    else         { SN += E2[j]; NNa += P2[j]; }
  }
  const float f1 = __expf(ad), f2 = __expf(0.2f * ad);
  out[b * NN + tid] = (f1 * NP + f2 * NNa) / (f1 * SP + f2 * SN) + b2[0];
}

// ================================ launch ======================================
extern "C" void kernel_launch(void* const* d_in, const int* in_sizes, int n_in,
                              void* d_out, int out_size) {
  const float* x    = (const float*)d_in[0];
  const float* W1   = (const float*)d_in[2];
  const float* as1  = (const float*)d_in[3];
  const float* ad1  = (const float*)d_in[4];
  const float* b1   = (const float*)d_in[5];
  const float* gam  = (const float*)d_in[6];
  const float* bet  = (const float*)d_in[7];
  const float* W2   = (const float*)d_in[8];
  const float* as2  = (const float*)d_in[9];
  const float* ad2  = (const float*)d_in[10];
  const float* b2   = (const float*)d_in[11];
  float* out = (float*)d_out;

  cudaFuncSetAttribute(k1_gemm, cudaFuncAttributeMaxDynamicSharedMemorySize, K1_SMEM);

  k1_gemm<<<dim3(512, 4, 1), 256, K1_SMEM>>>(x, W1, as1, ad1);
  k2_sweep<<<BB * HH, 256>>>(b1);
  k3_ln<<<BB * NN / 8, 256>>>(gam, bet, W2);
  k4_attn2<<<BB, 256>>>(as2, ad2, b2, out);
}

// round 7
// speedup vs baseline: 1.7974x; 1.1848x over previous
#include <cuda_runtime.h>
#include <cuda_bf16.h>
#include <math.h>
#include <cstdint>

#define BB 256
#define NN 256
#define DIN 128
#define DHH 128
#define HH 4
#define HD 512

// ---------------- scratch (device globals; no allocation allowed) ----------------
__device__ float g_h[(size_t)BB * HH * NN * DHH];   // [b][h][j][d]
__device__ float g_as[BB * HH * NN];                // [b][h][n]
__device__ float g_ad[BB * HH * NN];
__device__ float g_y[(size_t)BB * NN * HD];         // [b][n][hd]
__device__ float g_hp[BB * NN];

// ================= Kernel 1 (mma.sync bf16x3): h = x @ W1 + a_s/a_d ==========
// grid 512: blockIdx.x -> (b, n-half). 8 warps x 16 rows = 128 rows; 4 head
// chunks of 128 cols. A/W staged in smem in mma-fragment order:
//   A 16B unit u = (wid*8 + ks)*32 + lane  -> regs {a0,a1,a2,a3}
//   B  8B unit u = (ks*16 + nt)*32 + lane  -> regs {b0,b1}
#define SM_ATT 0                       // att_src[512] + att_dst[512] fp32
#define SM_AHI 4096
#define SM_ALO (SM_AHI + 32768)
#define SM_WHI (SM_ALO + 32768)
#define SM_WLO (SM_WHI + 32768)
#define K1_SMEM (SM_WLO + 32768)

__device__ __forceinline__ void mma_bf16(float* c, uint32_t a0, uint32_t a1, uint32_t a2,
                                         uint32_t a3, uint32_t b0, uint32_t b1) {
  asm volatile(
      "mma.sync.aligned.m16n8k16.row.col.f32.bf16.bf16.f32 "
      "{%0,%1,%2,%3}, {%4,%5,%6,%7}, {%8,%9}, {%0,%1,%2,%3};\n"
      : "+f"(c[0]), "+f"(c[1]), "+f"(c[2]), "+f"(c[3])
      : "r"(a0), "r"(a1), "r"(a2), "r"(a3), "r"(b0), "r"(b1));
}
__device__ __forceinline__ uint32_t pack_bf16(float lo, float hi) {
  __nv_bfloat162 t(__float2bfloat16(lo), __float2bfloat16(hi));
  return *(uint32_t*)&t;
}

__global__ __launch_bounds__(256, 1) void k1_mma(
    const float* __restrict__ x, const float* __restrict__ W1,
    const float* __restrict__ att_src, const float* __restrict__ att_dst) {
  extern __shared__ char smem[];
  float* att = (float*)(smem + SM_ATT);
  const int tid = threadIdx.x;
  const int wid = tid >> 5, lane = tid & 31;
  const int g = lane >> 2, tig = lane & 3;
  const int bx = blockIdx.x;
  const int b = bx >> 1;
  const int n0 = (bx & 1) << 7;

  // att vectors -> smem
  {
    att[tid] = att_src[tid];
    att[256 + tid] = att_src[256 + tid];
    att[512 + tid] = att_dst[tid];
    att[768 + tid] = att_dst[256 + tid];
  }

  // ---- stage A (x rows n0..n0+127) as hi/lo bf16 fragments ----
  {
    const float* xg = x + (size_t)(b * NN + n0) * DIN;
    char* ahi = smem + SM_AHI;
    char* alo = smem + SM_ALO;
#pragma unroll
    for (int it = 0; it < 16; ++it) {
      int idx = it * 256 + tid;
      int row = idx >> 5;
      int k4 = (idx & 31) << 2;
      float4 v = *(const float4*)(xg + row * DIN + k4);
      float hx = __bfloat162float(__float2bfloat16(v.x));
      float hy = __bfloat162float(__float2bfloat16(v.y));
      float hz = __bfloat162float(__float2bfloat16(v.z));
      float hw = __bfloat162float(__float2bfloat16(v.w));
      uint32_t wh0 = pack_bf16(hx, hy), wh1 = pack_bf16(hz, hw);
      uint32_t wl0 = pack_bf16(v.x - hx, v.y - hy), wl1 = pack_bf16(v.z - hz, v.w - hw);
      int aw = row >> 4;              // warp row-block
      int ag = row & 7;               // fragment row within 8
      int areg = ((row & 15) >= 8 ? 1 : 0) + ((k4 & 15) >= 8 ? 2 : 0);
      int ks = k4 >> 4;
      int atig = (k4 & 7) >> 1;       // k4 in {0,4,8,12} -> tig {0,2,0,2}
      int t0 = ag * 4 + atig;
      uint32_t byte0 = (uint32_t)(((aw * 8 + ks) * 32 + t0) * 16 + areg * 4);
      uint32_t byte1 = (uint32_t)(((aw * 8 + ks) * 32 + t0 + 1) * 16 + areg * 4);
      *(uint32_t*)(ahi + byte0) = wh0;
      *(uint32_t*)(ahi + byte1) = wh1;
      *(uint32_t*)(alo + byte0) = wl0;
      *(uint32_t*)(alo + byte1) = wl1;
    }
  }

  const float* att_s = att;
  const float* att_d = att + 512;
  const int r0 = wid << 4;

  for (int ch = 0; ch < HH; ++ch) {
    __syncthreads();  // previous chunk's mma reads done before W overwrite
    // ---- stage W chunk (B = W1[:,ch,:]^T, [d][k]) as hi/lo fragments ----
    {
      char* whi = smem + SM_WHI;
      char* wlo = smem + SM_WLO;
      const int d = tid & 127;
      const int kbase = (tid >> 7) << 6;
      const int nt = d >> 3, wg = d & 7;
#pragma unroll 8
      for (int kk = 0; kk < 32; ++kk) {
        int k = kbase + (kk << 1);
        float w0 = __ldg(W1 + (size_t)(k * HH + ch) * DHH + d);
        float w1 = __ldg(W1 + (size_t)((k + 1) * HH + ch) * DHH + d);
        float h0 = __bfloat162float(__float2bfloat16(w0));
        float h1 = __bfloat162float(__float2bfloat16(w1));
        int ks = k >> 4;
        int kkm = k & 15;
        int btig = (kkm & 7) >> 1;
        int breg = (kkm >= 8) ? 1 : 0;
        int t = wg * 4 + btig;
        uint32_t byte = (uint32_t)(((ks * 16 + nt) * 32 + t) * 8 + breg * 4);
        *(uint32_t*)(whi + byte) = pack_bf16(h0, h1);
        *(uint32_t*)(wlo + byte) = pack_bf16(w0 - h0, w1 - h1);
      }
    }
    __syncthreads();

    // ---- mma mainloop: 8 ksteps x 16 ntiles x 3 splits ----
    float acc[16][4];
#pragma unroll
    for (int nt = 0; nt < 16; ++nt)
#pragma unroll
      for (int q = 0; q < 4; ++q) acc[nt][q] = 0.f;

    const uint4* ahiF = (const uint4*)(smem + SM_AHI);
    const uint4* aloF = (const uint4*)(smem + SM_ALO);
    const uint2* whiF = (const uint2*)(smem + SM_WHI);
    const uint2* wloF = (const uint2*)(smem + SM_WLO);

#pragma unroll
    for (int ks = 0; ks < 8; ++ks) {
      uint4 Ah = ahiF[(wid * 8 + ks) * 32 + lane];
      uint4 Al = aloF[(wid * 8 + ks) * 32 + lane];
#pragma unroll
      for (int nt = 0; nt < 16; ++nt) {
        uint2 Bh = whiF[(ks * 16 + nt) * 32 + lane];
        uint2 Bl = wloF[(ks * 16 + nt) * 32 + lane];
        mma_bf16(acc[nt], Ah.x, Ah.y, Ah.z, Ah.w, Bh.x, Bh.y);
        mma_bf16(acc[nt], Ah.x, Ah.y, Ah.z, Ah.w, Bl.x, Bl.y);
        mma_bf16(acc[nt], Al.x, Al.y, Al.z, Al.w, Bh.x, Bh.y);
      }
    }

    // ---- epilogue: att dots + h stores ----
    float as0 = 0.f, as8 = 0.f, ad0 = 0.f, ad8 = 0.f;
    float* hrow0 = g_h + (size_t)((b * HH + ch) * NN + n0 + r0 + g) * DHH;
    float* hrow8 = hrow0 + (size_t)8 * DHH;
#pragma unroll
    for (int nt = 0; nt < 16; ++nt) {
      int c = (nt << 3) + (tig << 1);
      float s0 = att_s[(ch << 7) + c], s1 = att_s[(ch << 7) + c + 1];
      float d0 = att_d[(ch << 7) + c], d1 = att_d[(ch << 7) + c + 1];
      as0 = fmaf(acc[nt][0], s0, fmaf(acc[nt][1], s1, as0));
      ad0 = fmaf(acc[nt][0], d0, fmaf(acc[nt][1], d1, ad0));
      as8 = fmaf(acc[nt][2], s0, fmaf(acc[nt][3], s1, as8));
      ad8 = fmaf(acc[nt][2], d0, fmaf(acc[nt][3], d1, ad8));
      *(float2*)(hrow0 + c) = make_float2(acc[nt][0], acc[nt][1]);
      *(float2*)(hrow8 + c) = make_float2(acc[nt][2], acc[nt][3]);
    }
#pragma unroll
    for (int off = 1; off <= 2; off <<= 1) {
      as0 += __shfl_xor_sync(0xffffffffu, as0, off);
      ad0 += __shfl_xor_sync(0xffffffffu, ad0, off);
      as8 += __shfl_xor_sync(0xffffffffu, as8, off);
      ad8 += __shfl_xor_sync(0xffffffffu, ad8, off);
    }
    if (tig == 0) {
      size_t base = (size_t)(b * HH + ch) * NN + n0 + r0 + g;
      g_as[base] = as0;
      g_ad[base] = ad0;
      g_as[base + 8] = as8;
      g_ad[base + 8] = ad8;
    }
  }
}

// ================= Kernel 2 v2: chunked sorted-prefix softmax aggregation ======
__global__ __launch_bounds__(256, 4) void k2_sweep(const float* __restrict__ b1) {
  __shared__ float skey[NN];
  __shared__ int   jidx[NN];
  __shared__ float E1s[NN], E2s[NN];
  __shared__ float cS1[NN + 1], cS2[NN + 1];
  __shared__ float stmp[16];
  __shared__ float F1v[NN], F2v[NN];
  __shared__ int   ckey[NN];
  __shared__ int   startv[18];
  __shared__ float CP1[17 * 128], CP2[17 * 128];
  __shared__ float hbuf[16 * 128];

  const int bh = blockIdx.x;
  const int h = bh & 3;
  const int b = bh >> 2;
  const int tid = threadIdx.x;
  const int lane = tid & 31, warp = tid >> 5;
  const float* hb = g_h + (size_t)bh * NN * DHH;

  skey[tid] = g_as[bh * NN + tid];
  jidx[tid] = tid;
  __syncthreads();

#pragma unroll
  for (int size = 2; size <= NN; size <<= 1) {
#pragma unroll
    for (int stride = size >> 1; stride > 0; stride >>= 1) {
      int partner = tid ^ stride;
      if (partner > tid) {
        bool asc = ((tid & size) == 0);
        float k0 = skey[tid], k1 = skey[partner];
        if ((k0 > k1) == asc) {
          skey[tid] = k1; skey[partner] = k0;
          int j0 = jidx[tid], j1 = jidx[partner];
          jidx[tid] = j1; jidx[partner] = j0;
        }
      }
      __syncthreads();
    }
  }

  {
    float k = skey[tid];
    E1s[tid] = __expf(k);
    E2s[tid] = __expf(0.2f * k);
  }
  __syncthreads();

  {
    float v1 = E1s[tid], v2 = E2s[tid];
#pragma unroll
    for (int off = 1; off < 32; off <<= 1) {
      float n1 = __shfl_up_sync(0xffffffffu, v1, off);
      float n2 = __shfl_up_sync(0xffffffffu, v2, off);
      if (lane >= off) { v1 += n1; v2 += n2; }
    }
    if (lane == 31) { stmp[warp] = v1; stmp[8 + warp] = v2; }
    __syncthreads();
    if (warp == 0 && lane < 8) {
      float w1 = stmp[lane], w2 = stmp[8 + lane];
#pragma unroll
      for (int off = 1; off < 8; off <<= 1) {
        float n1 = __shfl_up_sync(0xffu, w1, off);
        float n2 = __shfl_up_sync(0xffu, w2, off);
        if (lane >= off) { w1 += n1; w2 += n2; }
      }
      stmp[lane] = w1; stmp[8 + lane] = w2;
    }
    __syncthreads();
    float base1 = (warp > 0) ? stmp[warp - 1] : 0.f;
    float base2 = (warp > 0) ? stmp[8 + warp - 1] : 0.f;
    cS1[tid + 1] = v1 + base1;
    cS2[tid + 1] = v2 + base2;
    if (tid == 0) { cS1[0] = 0.f; cS2[0] = 0.f; }
  }
  __syncthreads();

  {
    const float ad = g_ad[bh * NN + tid];
    const float xneg = -ad;
    int lo = 0, hi = NN;
#pragma unroll
    for (int s = 0; s < 8; ++s) {
      int mid = (lo + hi) >> 1;
      if (skey[mid] > xneg) hi = mid; else lo = mid + 1;
    }
    int c = lo;
    float SP = cS1[NN] - cS1[c];
    float SN = cS2[c];
    float f1 = __expf(ad);
    float f2 = __expf(0.2f * ad);
    float r = 1.0f / (f1 * SP + f2 * SN);
    F1v[tid] = f1 * r;
    F2v[tid] = f2 * r;
    ckey[tid] = (c << 16) | tid;
  }
  __syncthreads();

  {
    const int d = tid & 127, half = tid >> 7;
#pragma unroll
    for (int cc = 0; cc < 8; ++cc) {
      const int c = half * 8 + cc;
      float s1 = 0.f, s2 = 0.f;
#pragma unroll
      for (int t = 0; t < 16; ++t) {
        int p = (c << 4) + t;
        int jp = jidx[p];
        float hv = __ldg(hb + (size_t)jp * DHH + d);
        s1 = fmaf(E1s[p], hv, s1);
        s2 = fmaf(E2s[p], hv, s2);
      }
      CP1[(c + 1) * 128 + d] = s1;
      CP2[(c + 1) * 128 + d] = s2;
    }
  }
  __syncthreads();
  if (tid < 128) {
    float run1 = 0.f, run2 = 0.f;
    CP1[tid] = 0.f; CP2[tid] = 0.f;
#pragma unroll
    for (int k = 1; k <= 16; ++k) {
      run1 += CP1[k * 128 + tid]; CP1[k * 128 + tid] = run1;
      run2 += CP2[k * 128 + tid]; CP2[k * 128 + tid] = run2;
    }
  }
  __syncthreads();

#pragma unroll
  for (int size = 2; size <= NN; size <<= 1) {
#pragma unroll
    for (int stride = size >> 1; stride > 0; stride >>= 1) {
      int partner = tid ^ stride;
      if (partner > tid) {
        bool asc = ((tid & size) == 0);
        int k0 = ckey[tid], k1 = ckey[partner];
        if ((k0 > k1) == asc) { ckey[tid] = k1; ckey[partner] = k0; }
      }
      __syncthreads();
    }
  }
  if (tid < 17) {
    int target = (tid * 16) << 16;
    int lo = 0, hi = NN;
    while (lo < hi) { int mid = (lo + hi) >> 1; if (ckey[mid] < target) lo = mid + 1; else hi = mid; }
    startv[tid] = lo;
  }
  if (tid == 17) startv[17] = NN;
  __syncthreads();

  const int tg = tid >> 7, d = tid & 127;
  const float bias_d = b1[(h << 7) + d];
  const float T1d = CP1[(16 << 7) + d];
  float* yb = g_y + (size_t)b * NN * HD + (h << 7) + d;

  for (int ch = 0; ch < 16; ++ch) {
    const int lo = startv[ch], hi = startv[ch + 1];
    __syncthreads();
    if (lo < hi) {
#pragma unroll
      for (int q = tid; q < 2048; q += 256) {
        int p = (ch << 4) + (q >> 7);
        int jp = jidx[p];
        hbuf[q] = __ldg(hb + (size_t)jp * DHH + (q & 127));
      }
    }
    __syncthreads();
    for (int r = lo + tg; r < hi; r += 2) {
      int ck = ckey[r];
      int i = ck & 0xffff;
      int c = ck >> 16;
      float P1 = CP1[(ch << 7) + d], P2 = CP2[(ch << 7) + d];
#pragma unroll 4
      for (int p = ch << 4; p < c; ++p) {
        float hv = hbuf[((p - (ch << 4)) << 7) + d];
        P1 = fmaf(E1s[p], hv, P1);
        P2 = fmaf(E2s[p], hv, P2);
      }
      yb[(size_t)i * HD] = fmaf(F1v[i], T1d - P1, F2v[i] * P2) + bias_d;
    }
  }
  {
    const float P2t = CP2[(16 << 7) + d];
    for (int r = startv[16] + tg; r < NN; r += 2) {
      int i = ckey[r] & 0xffff;
      yb[(size_t)i * HD] = F2v[i] * P2t + bias_d;
    }
  }
}

// ================= Kernel 3: LayerNorm + ELU + projection -> hp ===============
__global__ __launch_bounds__(256) void k3_ln(
    const float* __restrict__ gamma, const float* __restrict__ beta,
    const float* __restrict__ W2) {
  const int w = threadIdx.x >> 5, lane = threadIdx.x & 31;
  const int row = blockIdx.x * 8 + w;
  const float* yr = g_y + (size_t)row * HD;
  float4 v[4];
  float s = 0.f, sq = 0.f;
#pragma unroll
  for (int k = 0; k < 4; ++k) {
    v[k] = *(const float4*)(yr + (((k << 5) + lane) << 2));
    s += v[k].x + v[k].y + v[k].z + v[k].w;
    sq += v[k].x * v[k].x + v[k].y * v[k].y + v[k].z * v[k].z + v[k].w * v[k].w;
  }
#pragma unroll
  for (int off = 16; off > 0; off >>= 1) {
    s += __shfl_xor_sync(0xffffffffu, s, off);
    sq += __shfl_xor_sync(0xffffffffu, sq, off);
  }
  const float mu = s * (1.0f / 512.0f);
  const float var = sq * (1.0f / 512.0f) - mu * mu;
  const float rinv = rsqrtf(var + 1e-5f);
  float hp = 0.f;
#pragma unroll
  for (int k = 0; k < 4; ++k) {
    int c = (((k << 5) + lane) << 2);
    float4 g4 = *(const float4*)(gamma + c);
    float4 b4 = *(const float4*)(beta + c);
    float4 w4 = *(const float4*)(W2 + c);
    float t, e;
    t = (v[k].x - mu) * rinv * g4.x + b4.x; e = t > 0.f ? t : expm1f(t); hp = fmaf(e, w4.x, hp);
    t = (v[k].y - mu) * rinv * g4.y + b4.y; e = t > 0.f ? t : expm1f(t); hp = fmaf(e, w4.y, hp);
    t = (v[k].z - mu) * rinv * g4.z + b4.z; e = t > 0.f ? t : expm1f(t); hp = fmaf(e, w4.z, hp);
    t = (v[k].w - mu) * rinv * g4.w + b4.w; e = t > 0.f ? t : expm1f(t); hp = fmaf(e, w4.w, hp);
  }
#pragma unroll
  for (int off = 16; off > 0; off >>= 1) hp += __shfl_xor_sync(0xffffffffu, hp, off);
  if (lane == 0) g_hp[row] = hp;
}

// ================= Kernel 4: layer-2 scalar attention per batch ===============
__global__ __launch_bounds__(256) void k4_attn2(
    const float* __restrict__ att_src2, const float* __restrict__ att_dst2,
    const float* __restrict__ b2, float* __restrict__ out) {
  __shared__ float asv[NN], E1[NN], E2[NN], P1[NN], P2[NN];
  const int b = blockIdx.x, tid = threadIdx.x;
  const float v = g_hp[b * NN + tid];
  const float a_src = att_src2[0], a_dst = att_dst2[0];
  const float as = v * a_src;
  asv[tid] = as;
  const float e1 = __expf(as), e2 = __expf(0.2f * as);
  E1[tid] = e1; E2[tid] = e2; P1[tid] = e1 * v; P2[tid] = e2 * v;
  __syncthreads();
  const float ad = v * a_dst;
  float SP = 0.f, SN = 0.f, NP = 0.f, NNa = 0.f;
#pragma unroll 4
  for (int j = 0; j < NN; ++j) {
    float t = ad + asv[j];
    if (t > 0.f) { SP += E1[j]; NP += P1[j]; }
    else         { SN += E2[j]; NNa += P2[j]; }
  }
  const float f1 = __expf(ad), f2 = __expf(0.2f * ad);
  out[b * NN + tid] = (f1 * NP + f2 * NNa) / (f1 * SP + f2 * SN) + b2[0];
}

// ================================ launch ======================================
extern "C" void kernel_launch(void* const* d_in, const int* in_sizes, int n_in,
                              void* d_out, int out_size) {
  const float* x    = (const float*)d_in[0];
  const float* W1   = (const float*)d_in[2];
  const float* as1  = (const float*)d_in[3];
  const float* ad1  = (const float*)d_in[4];
  const float* b1   = (const float*)d_in[5];
  const float* gam  = (const float*)d_in[6];
  const float* bet  = (const float*)d_in[7];
  const float* W2   = (const float*)d_in[8];
  const float* as2  = (const float*)d_in[9];
  const float* ad2  = (const float*)d_in[10];
  const float* b2   = (const float*)d_in[11];
  float* out = (float*)d_out;

  cudaFuncSetAttribute(k1_mma, cudaFuncAttributeMaxDynamicSharedMemorySize, K1_SMEM);

  k1_mma<<<512, 256, K1_SMEM>>>(x, W1, as1, ad1);
  k2_sweep<<<BB * HH, 256>>>(b1);
  k3_ln<<<BB * NN / 8, 256>>>(gam, bet, W2);
  k4_attn2<<<BB, 256>>>(as2, ad2, b2, out);
}

// round 8
// speedup vs baseline: 2.5091x; 1.3960x over previous
#include <cuda_runtime.h>
#include <cuda_fp16.h>
#include <math.h>
#include <cstdint>

#define BB 256
#define NN 256
#define DIN 128
#define DHH 128
#define HH 4
#define HD 512

// ---------------- scratch (device globals; no allocation allowed) ----------------
__device__ float g_h[(size_t)BB * HH * NN * DHH];   // [b][h][j][d]
__device__ float g_as[BB * HH * NN];                // [b][h][n]
__device__ float g_ad[BB * HH * NN];
__device__ float g_y[(size_t)BB * NN * HD];         // [b][n][hd]
__device__ float g_hp[BB * NN];

// ================= Kernel 1 (mma.sync fp16x2): h = x @ W1 + a_s/a_d ==========
// A = x split hi+lo (fp16); W rounded to fp16. h = hiA*W16 + loA*W16.
// 8 warps x 16 rows; 4 head chunks of 128 cols. Fragment-order smem staging.
#define SM_ATT 0                       // att_src[512] + att_dst[512] fp32
#define SM_AHI 4096
#define SM_ALO (SM_AHI + 32768)
#define SM_WHI (SM_ALO + 32768)
#define K1_SMEM (SM_WHI + 32768)

__device__ __forceinline__ void mma_f16(float* c, uint32_t a0, uint32_t a1, uint32_t a2,
                                        uint32_t a3, uint32_t b0, uint32_t b1) {
  asm volatile(
      "mma.sync.aligned.m16n8k16.row.col.f32.f16.f16.f32 "
      "{%0,%1,%2,%3}, {%4,%5,%6,%7}, {%8,%9}, {%0,%1,%2,%3};\n"
      : "+f"(c[0]), "+f"(c[1]), "+f"(c[2]), "+f"(c[3])
      : "r"(a0), "r"(a1), "r"(a2), "r"(a3), "r"(b0), "r"(b1));
}
__device__ __forceinline__ uint32_t pack_f16(float lo, float hi) {
  __half2 t(__float2half(lo), __float2half(hi));
  return *(uint32_t*)&t;
}

__global__ __launch_bounds__(256, 2) void k1_mma(
    const float* __restrict__ x, const float* __restrict__ W1,
    const float* __restrict__ att_src, const float* __restrict__ att_dst) {
  extern __shared__ char smem[];
  float* att = (float*)(smem + SM_ATT);
  const int tid = threadIdx.x;
  const int wid = tid >> 5, lane = tid & 31;
  const int g = lane >> 2, tig = lane & 3;
  const int bx = blockIdx.x;
  const int b = bx >> 1;
  const int n0 = (bx & 1) << 7;

  // att vectors -> smem
  {
    att[tid] = att_src[tid];
    att[256 + tid] = att_src[256 + tid];
    att[512 + tid] = att_dst[tid];
    att[768 + tid] = att_dst[256 + tid];
  }

  // ---- stage A (x rows n0..n0+127) as hi/lo fp16 fragments ----
  {
    const float* xg = x + (size_t)(b * NN + n0) * DIN;
    char* ahi = smem + SM_AHI;
    char* alo = smem + SM_ALO;
#pragma unroll
    for (int it = 0; it < 16; ++it) {
      int idx = it * 256 + tid;
      int row = idx >> 5;
      int k4 = (idx & 31) << 2;
      float4 v = *(const float4*)(xg + row * DIN + k4);
      float hx = __half2float(__float2half(v.x));
      float hy = __half2float(__float2half(v.y));
      float hz = __half2float(__float2half(v.z));
      float hw = __half2float(__float2half(v.w));
      uint32_t wh0 = pack_f16(hx, hy), wh1 = pack_f16(hz, hw);
      uint32_t wl0 = pack_f16(v.x - hx, v.y - hy), wl1 = pack_f16(v.z - hz, v.w - hw);
      int aw = row >> 4;
      int ag = row & 7;
      int areg = ((row & 15) >= 8 ? 1 : 0) + ((k4 & 15) >= 8 ? 2 : 0);
      int ks = k4 >> 4;
      int atig = (k4 & 7) >> 1;
      int t0 = ag * 4 + atig;
      uint32_t byte0 = (uint32_t)(((aw * 8 + ks) * 32 + t0) * 16 + areg * 4);
      uint32_t byte1 = (uint32_t)(((aw * 8 + ks) * 32 + t0 + 1) * 16 + areg * 4);
      *(uint32_t*)(ahi + byte0) = wh0;
      *(uint32_t*)(ahi + byte1) = wh1;
      *(uint32_t*)(alo + byte0) = wl0;
      *(uint32_t*)(alo + byte1) = wl1;
    }
  }

  const float* att_s = att;
  const float* att_d = att + 512;
  const int r0 = wid << 4;

  for (int ch = 0; ch < HH; ++ch) {
    __syncthreads();  // previous chunk's mma reads done before W overwrite
    // ---- stage W chunk (B = W1[:,ch,:]^T, [d][k]) as fp16 fragments ----
    {
      char* whi = smem + SM_WHI;
      const int d = tid & 127;
      const int kbase = (tid >> 7) << 6;
      const int nt = d >> 3, wg = d & 7;
#pragma unroll 8
      for (int kk = 0; kk < 32; ++kk) {
        int k = kbase + (kk << 1);
        float w0 = __ldg(W1 + (size_t)(k * HH + ch) * DHH + d);
        float w1 = __ldg(W1 + (size_t)((k + 1) * HH + ch) * DHH + d);
        int ks = k >> 4;
        int kkm = k & 15;
        int btig = (kkm & 7) >> 1;
        int breg = (kkm >= 8) ? 1 : 0;
        int t = wg * 4 + btig;
        uint32_t byte = (uint32_t)(((ks * 16 + nt) * 32 + t) * 8 + breg * 4);
        *(uint32_t*)(whi + byte) = pack_f16(w0, w1);
      }
    }
    __syncthreads();

    // ---- mma mainloop: 8 ksteps x 16 ntiles x 2 splits ----
    float acc[16][4];
#pragma unroll
    for (int nt = 0; nt < 16; ++nt)
#pragma unroll
      for (int q = 0; q < 4; ++q) acc[nt][q] = 0.f;

    const uint4* ahiF = (const uint4*)(smem + SM_AHI);
    const uint4* aloF = (const uint4*)(smem + SM_ALO);
    const uint2* whiF = (const uint2*)(smem + SM_WHI);

#pragma unroll
    for (int ks = 0; ks < 8; ++ks) {
      uint4 Ah = ahiF[(wid * 8 + ks) * 32 + lane];
      uint4 Al = aloF[(wid * 8 + ks) * 32 + lane];
#pragma unroll
      for (int nt = 0; nt < 16; ++nt) {
        uint2 Bh = whiF[(ks * 16 + nt) * 32 + lane];
        mma_f16(acc[nt], Ah.x, Ah.y, Ah.z, Ah.w, Bh.x, Bh.y);
        mma_f16(acc[nt], Al.x, Al.y, Al.z, Al.w, Bh.x, Bh.y);
      }
    }

    // ---- epilogue: att dots + h stores ----
    float as0 = 0.f, as8 = 0.f, ad0 = 0.f, ad8 = 0.f;
    float* hrow0 = g_h + (size_t)((b * HH + ch) * NN + n0 + r0 + g) * DHH;
    float* hrow8 = hrow0 + (size_t)8 * DHH;
#pragma unroll
    for (int nt = 0; nt < 16; ++nt) {
      int c = (nt << 3) + (tig << 1);
      float s0 = att_s[(ch << 7) + c], s1 = att_s[(ch << 7) + c + 1];
      float d0 = att_d[(ch << 7) + c], d1 = att_d[(ch << 7) + c + 1];
      as0 = fmaf(acc[nt][0], s0, fmaf(acc[nt][1], s1, as0));
      ad0 = fmaf(acc[nt][0], d0, fmaf(acc[nt][1], d1, ad0));
      as8 = fmaf(acc[nt][2], s0, fmaf(acc[nt][3], s1, as8));
      ad8 = fmaf(acc[nt][2], d0, fmaf(acc[nt][3], d1, ad8));
      *(float2*)(hrow0 + c) = make_float2(acc[nt][0], acc[nt][1]);
      *(float2*)(hrow8 + c) = make_float2(acc[nt][2], acc[nt][3]);
    }
#pragma unroll
    for (int off = 1; off <= 2; off <<= 1) {
      as0 += __shfl_xor_sync(0xffffffffu, as0, off);
      ad0 += __shfl_xor_sync(0xffffffffu, ad0, off);
      as8 += __shfl_xor_sync(0xffffffffu, as8, off);
      ad8 += __shfl_xor_sync(0xffffffffu, ad8, off);
    }
    if (tig == 0) {
      size_t base = (size_t)(b * HH + ch) * NN + n0 + r0 + g;
      g_as[base] = as0;
      g_ad[base] = ad0;
      g_as[base + 8] = as8;
      g_ad[base + 8] = ad8;
    }
  }
}

// ================= Kernel 2 v3: chunked sorted-prefix + cp.async double buffer ==
__device__ __forceinline__ uint32_t smem_u32_k2(const void* p) {
  uint32_t a;
  asm("{ .reg .u64 t; cvta.to.shared.u64 t, %1; cvt.u32.u64 %0, t; }" : "=r"(a) : "l"(p));
  return a;
}
__device__ __forceinline__ void cp16(uint32_t dst, const void* src) {
  asm volatile("cp.async.cg.shared.global [%0], [%1], 16;" :: "r"(dst), "l"(src) : "memory");
}
#define CP_COMMIT() asm volatile("cp.async.commit_group;" ::: "memory")
#define CP_WAIT(n)  asm volatile("cp.async.wait_group %0;" :: "n"(n) : "memory")

__global__ __launch_bounds__(256, 4) void k2_sweep(const float* __restrict__ b1) {
  __shared__ float skey[NN];
  __shared__ int   jidx[NN];
  __shared__ float E1s[NN], E2s[NN];
  __shared__ float cS1[NN + 1], cS2[NN + 1];
  __shared__ float stmp[16];
  __shared__ float F1v[NN], F2v[NN];
  __shared__ int   ckey[NN];
  __shared__ int   startv[18];
  __shared__ float CP1[17 * 128], CP2[17 * 128];
  __shared__ float hbuf[2][16 * 128];

  const int bh = blockIdx.x;
  const int h = bh & 3;
  const int b = bh >> 2;
  const int tid = threadIdx.x;
  const int lane = tid & 31, warp = tid >> 5;
  const float* hb = g_h + (size_t)bh * NN * DHH;
  const uint32_t hbuf_addr = smem_u32_k2(hbuf);

  skey[tid] = g_as[bh * NN + tid];
  jidx[tid] = tid;
  __syncthreads();

#pragma unroll
  for (int size = 2; size <= NN; size <<= 1) {
#pragma unroll
    for (int stride = size >> 1; stride > 0; stride >>= 1) {
      int partner = tid ^ stride;
      if (partner > tid) {
        bool asc = ((tid & size) == 0);
        float k0 = skey[tid], k1 = skey[partner];
        if ((k0 > k1) == asc) {
          skey[tid] = k1; skey[partner] = k0;
          int j0 = jidx[tid], j1 = jidx[partner];
          jidx[tid] = j1; jidx[partner] = j0;
        }
      }
      __syncthreads();
    }
  }

  {
    float k = skey[tid];
    E1s[tid] = __expf(k);
    E2s[tid] = __expf(0.2f * k);
  }
  __syncthreads();

  {
    float v1 = E1s[tid], v2 = E2s[tid];
#pragma unroll
    for (int off = 1; off < 32; off <<= 1) {
      float n1 = __shfl_up_sync(0xffffffffu, v1, off);
      float n2 = __shfl_up_sync(0xffffffffu, v2, off);
      if (lane >= off) { v1 += n1; v2 += n2; }
    }
    if (lane == 31) { stmp[warp] = v1; stmp[8 + warp] = v2; }
    __syncthreads();
    if (warp == 0 && lane < 8) {
      float w1 = stmp[lane], w2 = stmp[8 + lane];
#pragma unroll
      for (int off = 1; off < 8; off <<= 1) {
        float n1 = __shfl_up_sync(0xffu, w1, off);
        float n2 = __shfl_up_sync(0xffu, w2, off);
        if (lane >= off) { w1 += n1; w2 += n2; }
      }
      stmp[lane] = w1; stmp[8 + lane] = w2;
    }
    __syncthreads();
    float base1 = (warp > 0) ? stmp[warp - 1] : 0.f;
    float base2 = (warp > 0) ? stmp[8 + warp - 1] : 0.f;
    cS1[tid + 1] = v1 + base1;
    cS2[tid + 1] = v2 + base2;
    if (tid == 0) { cS1[0] = 0.f; cS2[0] = 0.f; }
  }
  __syncthreads();

  {
    const float ad = g_ad[bh * NN + tid];
    const float xneg = -ad;
    int lo = 0, hi = NN;
#pragma unroll
    for (int s = 0; s < 8; ++s) {
      int mid = (lo + hi) >> 1;
      if (skey[mid] > xneg) hi = mid; else lo = mid + 1;
    }
    int c = lo;
    float SP = cS1[NN] - cS1[c];
    float SN = cS2[c];
    float f1 = __expf(ad);
    float f2 = __expf(0.2f * ad);
    float r = 1.0f / (f1 * SP + f2 * SN);
    F1v[tid] = f1 * r;
    F2v[tid] = f2 * r;
    ckey[tid] = (c << 16) | tid;
  }
  __syncthreads();

  // ---- vector chunk checkpoints ----
  {
    const int d = tid & 127, half = tid >> 7;
#pragma unroll
    for (int cc = 0; cc < 8; ++cc) {
      const int c = half * 8 + cc;
      float s1 = 0.f, s2 = 0.f;
#pragma unroll
      for (int t = 0; t < 16; ++t) {
        int p = (c << 4) + t;
        int jp = jidx[p];
        float hv = __ldg(hb + (size_t)jp * DHH + d);
        s1 = fmaf(E1s[p], hv, s1);
        s2 = fmaf(E2s[p], hv, s2);
      }
      CP1[(c + 1) * 128 + d] = s1;
      CP2[(c + 1) * 128 + d] = s2;
    }
  }

  // prefetch chunk 0 rows into hbuf[0] while sort2 runs
  {
#pragma unroll
    for (int rep = 0; rep < 2; ++rep) {
      int u = rep * 256 + tid;
      int t = u >> 5, d4 = u & 31;
      int jp = jidx[t];
      cp16(hbuf_addr + (uint32_t)u * 16u, hb + (size_t)jp * DHH + d4 * 4);
    }
    CP_COMMIT();
  }

  __syncthreads();
  if (tid < 128) {
    float run1 = 0.f, run2 = 0.f;
    CP1[tid] = 0.f; CP2[tid] = 0.f;
#pragma unroll
    for (int k = 1; k <= 16; ++k) {
      run1 += CP1[k * 128 + tid]; CP1[k * 128 + tid] = run1;
      run2 += CP2[k * 128 + tid]; CP2[k * 128 + tid] = run2;
    }
  }
  __syncthreads();

  // ---- bitonic sort #2: ckey asc ----
#pragma unroll
  for (int size = 2; size <= NN; size <<= 1) {
#pragma unroll
    for (int stride = size >> 1; stride > 0; stride >>= 1) {
      int partner = tid ^ stride;
      if (partner > tid) {
        bool asc = ((tid & size) == 0);
        int k0 = ckey[tid], k1 = ckey[partner];
        if ((k0 > k1) == asc) { ckey[tid] = k1; ckey[partner] = k0; }
      }
      __syncthreads();
    }
  }
  if (tid < 17) {
    int target = (tid * 16) << 16;
    int lo = 0, hi = NN;
    while (lo < hi) { int mid = (lo + hi) >> 1; if (ckey[mid] < target) lo = mid + 1; else hi = mid; }
    startv[tid] = lo;
  }
  if (tid == 17) startv[17] = NN;
  __syncthreads();

  // ---- emission: 16 double-buffered phases + exact tail ----
  const int tg = tid >> 7, d = tid & 127;
  const float bias_d = b1[(h << 7) + d];
  const float T1d = CP1[(16 << 7) + d];
  float* yb = g_y + (size_t)b * NN * HD + (h << 7) + d;

  for (int ch = 0; ch < 16; ++ch) {
    if (ch < 15) {  // stage chunk ch+1 into the other buffer
      uint32_t hdst = hbuf_addr + (uint32_t)(((ch + 1) & 1) * 8192);
#pragma unroll
      for (int rep = 0; rep < 2; ++rep) {
        int u = rep * 256 + tid;
        int t = u >> 5, d4 = u & 31;
        int jp = jidx[((ch + 1) << 4) + t];
        cp16(hdst + (uint32_t)u * 16u, hb + (size_t)jp * DHH + d4 * 4);
      }
      CP_COMMIT();
      CP_WAIT(1);
    } else {
      CP_WAIT(0);
    }
    __syncthreads();

    const float* hs = hbuf[ch & 1];
    const int lo = startv[ch], hi = startv[ch + 1];
    const float P1b = CP1[(ch << 7) + d], P2b = CP2[(ch << 7) + d];
    for (int r = lo + tg; r < hi; r += 2) {
      int ck = ckey[r];
      int i = ck & 0xffff;
      int c = ck >> 16;
      float P1 = P1b, P2 = P2b;
#pragma unroll 4
      for (int p = ch << 4; p < c; ++p) {
        float hv = hs[((p - (ch << 4)) << 7) + d];
        P1 = fmaf(E1s[p], hv, P1);
        P2 = fmaf(E2s[p], hv, P2);
      }
      yb[(size_t)i * HD] = fmaf(F1v[i], T1d - P1, F2v[i] * P2) + bias_d;
    }
    __syncthreads();  // phase done before its buffer is re-staged
  }
  {
    const float P2t = CP2[(16 << 7) + d];
    for (int r = startv[16] + tg; r < NN; r += 2) {
      int i = ckey[r] & 0xffff;
      yb[(size_t)i * HD] = F2v[i] * P2t + bias_d;
    }
  }
}

// ================= Kernel 3: LayerNorm + ELU + projection -> hp ===============
__global__ __launch_bounds__(256) void k3_ln(
    const float* __restrict__ gamma, const float* __restrict__ beta,
    const float* __restrict__ W2) {
  const int w = threadIdx.x >> 5, lane = threadIdx.x & 31;
  const int row = blockIdx.x * 8 + w;
  const float* yr = g_y + (size_t)row * HD;
  float4 v[4];
  float s = 0.f, sq = 0.f;
#pragma unroll
  for (int k = 0; k < 4; ++k) {
    v[k] = *(const float4*)(yr + (((k << 5) + lane) << 2));
    s += v[k].x + v[k].y + v[k].z + v[k].w;
    sq += v[k].x * v[k].x + v[k].y * v[k].y + v[k].z * v[k].z + v[k].w * v[k].w;
  }
#pragma unroll
  for (int off = 16; off > 0; off >>= 1) {
    s += __shfl_xor_sync(0xffffffffu, s, off);
    sq += __shfl_xor_sync(0xffffffffu, sq, off);
  }
  const float mu = s * (1.0f / 512.0f);
  const float var = sq * (1.0f / 512.0f) - mu * mu;
  const float rinv = rsqrtf(var + 1e-5f);
  float hp = 0.f;
#pragma unroll
  for (int k = 0; k < 4; ++k) {
    int c = (((k << 5) + lane) << 2);
    float4 g4 = *(const float4*)(gamma + c);
    float4 b4 = *(const float4*)(beta + c);
    float4 w4 = *(const float4*)(W2 + c);
    float t, e;
    t = (v[k].x - mu) * rinv * g4.x + b4.x; e = t > 0.f ? t : expm1f(t); hp = fmaf(e, w4.x, hp);
    t = (v[k].y - mu) * rinv * g4.y + b4.y; e = t > 0.f ? t : expm1f(t); hp = fmaf(e, w4.y, hp);
    t = (v[k].z - mu) * rinv * g4.z + b4.z; e = t > 0.f ? t : expm1f(t); hp = fmaf(e, w4.z, hp);
    t = (v[k].w - mu) * rinv * g4.w + b4.w; e = t > 0.f ? t : expm1f(t); hp = fmaf(e, w4.w, hp);
  }
#pragma unroll
  for (int off = 16; off > 0; off >>= 1) hp += __shfl_xor_sync(0xffffffffu, hp, off);
  if (lane == 0) g_hp[row] = hp;
}

// ================= Kernel 4: layer-2 scalar attention per batch ===============
__global__ __launch_bounds__(256) void k4_attn2(
    const float* __restrict__ att_src2, const float* __restrict__ att_dst2,
    const float* __restrict__ b2, float* __restrict__ out) {
  __shared__ float asv[NN], E1[NN], E2[NN], P1[NN], P2[NN];
  const int b = blockIdx.x, tid = threadIdx.x;
  const float v = g_hp[b * NN + tid];
  const float a_src = att_src2[0], a_dst = att_dst2[0];
  const float as = v * a_src;
  asv[tid] = as;
  const float e1 = __expf(as), e2 = __expf(0.2f * as);
  E1[tid] = e1; E2[tid] = e2; P1[tid] = e1 * v; P2[tid] = e2 * v;
  __syncthreads();
  const float ad = v * a_dst;
  float SP = 0.f, SN = 0.f, NP = 0.f, NNa = 0.f;
#pragma unroll 4
  for (int j = 0; j < NN; ++j) {
    float t = ad + asv[j];
    if (t > 0.f) { SP += E1[j]; NP += P1[j]; }
    else         { SN += E2[j]; NNa += P2[j]; }
  }
  const float f1 = __expf(ad), f2 = __expf(0.2f * ad);
  out[b * NN + tid] = (f1 * NP + f2 * NNa) / (f1 * SP + f2 * SN) + b2[0];
}

// ================================ launch ======================================
extern "C" void kernel_launch(void* const* d_in, const int* in_sizes, int n_in,
                              void* d_out, int out_size) {
  const float* x    = (const float*)d_in[0];
  const float* W1   = (const float*)d_in[2];
  const float* as1  = (const float*)d_in[3];
  const float* ad1  = (const float*)d_in[4];
  const float* b1   = (const float*)d_in[5];
  const float* gam  = (const float*)d_in[6];
  const float* bet  = (const float*)d_in[7];
  const float* W2   = (const float*)d_in[8];
  const float* as2  = (const float*)d_in[9];
  const float* ad2  = (const float*)d_in[10];
  const float* b2   = (const float*)d_in[11];
  float* out = (float*)d_out;

  cudaFuncSetAttribute(k1_mma, cudaFuncAttributeMaxDynamicSharedMemorySize, K1_SMEM);

  k1_mma<<<512, 256, K1_SMEM>>>(x, W1, as1, ad1);
  k2_sweep<<<BB * HH, 256>>>(b1);
  k3_ln<<<BB * NN / 8, 256>>>(gam, bet, W2);
  k4_attn2<<<BB, 256>>>(as2, ad2, b2, out);
}